// round 14
// baseline (speedup 1.0000x reference)
#include <cuda_runtime.h>
#include <cuda_fp16.h>
#include <cstdint>

#define B 8
#define N 4096
#define D 1024
#define H 1024
#define NQ 64
#define H2 2048
#define TOPK 1024

// ---------------- scratch ----------------------------------------------------
__device__ __align__(16) float g_QWf[NQ * D];     // fp32 QW [q][d]
__device__ __align__(16) uint4 g_Bfrag[16384];    // fp16 fragment-ordered B (2 planes/word)
__device__ float g_qbi[NQ];                       // qb/32 + b2
__device__ __align__(16) float g_St[B * N * NQ];  // scores token-major
__device__ float g_pmax[B * 32 * NQ];
__device__ float g_psum[B * 32 * NQ];
__device__ float g_c[B * NQ];                     // final logsumexp constants
__device__ int   g_cnt[16];                       // last-CTA counters (reset in k_prep)
__device__ float g_imp[B * N];
__device__ int   g_flag[B * N];
__device__ int   g_idx[B * TOPK];
__device__ float g_C1, g_C2;
__device__ int   g_bz;

// ---------------- helpers ----------------------------------------------------
__device__ __forceinline__ uint32_t pack_h2(float a, float b) {
    __half2 h = __floats2half2_rn(a, b);
    return *reinterpret_cast<uint32_t*>(&h);
}
__device__ __forceinline__ float2 unpack_h2(uint32_t u) {
    __half2 h = *reinterpret_cast<__half2*>(&u);
    return __half22float2(h);
}
__device__ __forceinline__ void mma_f16(float* d, const uint32_t* a, uint32_t b0, uint32_t b1) {
    asm volatile("mma.sync.aligned.m16n8k16.row.col.f32.f16.f16.f32 "
        "{%0,%1,%2,%3}, {%4,%5,%6,%7}, {%8,%9}, {%0,%1,%2,%3};"
        : "+f"(d[0]), "+f"(d[1]), "+f"(d[2]), "+f"(d[3])
        : "r"(a[0]), "r"(a[1]), "r"(a[2]), "r"(a[3]), "r"(b0), "r"(b1));
}
__device__ __forceinline__ void cp_async16(void* dst_smem, const void* src) {
    uint32_t d;
    asm("{ .reg .u64 t; cvta.to.shared.u64 t, %1; cvt.u32.u64 %0, t; }" : "=r"(d) : "l"(dst_smem));
    asm volatile("cp.async.cg.shared.global [%0], [%1], 16;" :: "r"(d), "l"(src) : "memory");
}
#define CP_COMMIT() asm volatile("cp.async.commit_group;" ::: "memory")
#define CP_WAIT(n)  asm volatile("cp.async.wait_group %0;" :: "n"(n) : "memory")

// ---------------- kernel 0: prep (QW GEMM + qbi + density consts) ------------
__global__ void __launch_bounds__(256) k_prep(const float* __restrict__ qe,
                                              const float* __restrict__ kw,
                                              const float* __restrict__ kb,
                                              const float* __restrict__ b2,
                                              const float* __restrict__ w1,
                                              const float* __restrict__ b1,
                                              const float* __restrict__ w2) {
    int tid = threadIdx.x;
    int bid = blockIdx.x;
    if (bid < 128) {
        __shared__ float skw[8][68];
        __shared__ float sqt[64][65];
        int d0 = bid * 8;
        int q = tid & 63, dp = tid >> 6;
        float acc0 = 0.f, acc1 = 0.f;
        for (int k0 = 0; k0 < H; k0 += 64) {
#pragma unroll
            for (int r = 0; r < 2; r++) {
                int idx = tid + 256 * r;
                skw[idx >> 6][idx & 63] = kw[(size_t)(d0 + (idx >> 6)) * H + k0 + (idx & 63)];
            }
#pragma unroll
            for (int r = 0; r < 4; r++) {
                int idx = tid + 256 * r;
                int row = idx >> 4, c4 = (idx & 15) * 4;
                float4 v = *(const float4*)(qe + (size_t)row * H + k0 + c4);
                sqt[c4 + 0][row] = v.x; sqt[c4 + 1][row] = v.y;
                sqt[c4 + 2][row] = v.z; sqt[c4 + 3][row] = v.w;
            }
            __syncthreads();
#pragma unroll 8
            for (int k = 0; k < 64; k++) {
                float qv = sqt[k][q];
                acc0 = fmaf(skw[dp][k], qv, acc0);
                acc1 = fmaf(skw[dp + 4][k], qv, acc1);
            }
            __syncthreads();
        }
        g_QWf[(size_t)q * D + d0 + dp] = acc0;
        g_QWf[(size_t)q * D + d0 + dp + 4] = acc1;
    } else if (bid == 128) {
        if (tid < 16) g_cnt[tid] = 0;         // reset last-CTA counters (graph replay safe)
        int w = tid >> 5, l = tid & 31;
        float b2v = b2[0];
#pragma unroll
        for (int qi = 0; qi < 8; qi++) {
            int q = w * 8 + qi;
            float acc = 0.f;
#pragma unroll
            for (int k = 0; k < 32; k++)
                acc = fmaf(qe[(size_t)q * H + k * 32 + l], kb[k * 32 + l], acc);
#pragma unroll
            for (int o = 16; o; o >>= 1) acc += __shfl_xor_sync(~0u, acc, o);
            if (l == 0) g_qbi[q] = acc * 0.03125f + b2v;
        }
    } else {
        __shared__ float r1[256], r2[256];
        __shared__ int rz[256];
        float c1 = 0.f, c2 = 0.f; int bz = 1;
        for (int j = tid; j < H2; j += 256) {
            float a = w1[j], c = w2[j];
            if (a > 0.f) c1 += a * c; else c2 += a * c;
            if (b1[j] != 0.f) bz = 0;
        }
        r1[tid] = c1; r2[tid] = c2; rz[tid] = bz;
        __syncthreads();
        for (int o = 128; o; o >>= 1) {
            if (tid < o) { r1[tid] += r1[tid + o]; r2[tid] += r2[tid + o]; rz[tid] &= rz[tid + o]; }
            __syncthreads();
        }
        if (tid == 0) { g_C1 = r1[0]; g_C2 = r2[0]; g_bz = rz[0]; }
    }
}

// ---------------- kernel 1: pack B into fp16 fragment order (uint4) ----------
__global__ void k_bfrag() {
    int t = blockIdx.x * 256 + threadIdx.x;   // < 16384
    int lane = t & 31, j = (t >> 5) & 7, s = (t >> 8) & 1, c = t >> 9;
    int q = j * 8 + (lane >> 2);
    int k0 = c * 32 + s * 16 + (lane & 3) * 2;
    const float* w = g_QWf + (size_t)q * D + k0;
    float f0 = w[0], f1 = w[1], f2 = w[8], f3 = w[9];
    uint32_t ha = pack_h2(f0, f1), hb = pack_h2(f2, f3);
    float2 ca = unpack_h2(ha), cb = unpack_h2(hb);
    uint32_t ra = pack_h2(f0 - ca.x, f1 - ca.y);
    uint32_t rb = pack_h2(f2 - cb.x, f3 - cb.y);
    g_Bfrag[t] = make_uint4(ha, hb, ra, rb);   // plane0 | plane1 interleaved
}

// ---------------- kernel 2: score GEMM (3-stage, frag-B, last-CTA combine) ---
// float offsets in dynamic smem
#define XB(s)  ((s) * 4096)            // 3 X buffers, 128 rows x 32 (swizzled)
#define PM_OFF 9216                    // inside XB region; free after mainloop
#define PZ_OFF 9472
#define FLAG_OFF 9728
#define BBF(s) (12288 + (s) * 2048)    // 3 B fragment buffers (512 uint4)
#define SDB_OFF 18432
#define QBI_OFF 18560
#define SCORE_SMEM 74496               // 18624 floats

__global__ void __launch_bounds__(256, 3) k_score_tc(const float* __restrict__ x,
                                                     const float* __restrict__ dens,
                                                     const float* __restrict__ w1,
                                                     const float* __restrict__ b1,
                                                     const float* __restrict__ w2) {
    extern __shared__ float sm[];
    int tid = threadIdx.x, w = tid >> 5, l = tid & 31;
    int b = blockIdx.x >> 5, tile = blockIdx.x & 31;
    int n0 = tile << 7;
    int wm = w & 3, wn = w >> 2;
    const char* xg = (const char*)(x + ((size_t)(b * N + n0)) * D);
    const char* fg = (const char*)g_Bfrag;

    float acc[2][4][4] = {};

    int xrow = tid >> 1;                 // 0..127
    int xc0  = (tid & 1) * 4;            // chunk base 0 or 4

    auto issue = [&](int c) {
        int st = c % 3;
        float* xb = sm + XB(st);
        float* bb = sm + BBF(st);
#pragma unroll
        for (int i = 0; i < 4; i++) {
            int ch = xc0 + i;
            int chs = ch ^ ((xrow & 3) << 1);           // swizzled 16B chunk
            cp_async16(xb + xrow * 32 + chs * 4,
                       xg + (size_t)xrow * 4096 + (size_t)c * 128 + ch * 16);
        }
#pragma unroll
        for (int i = 0; i < 2; i++)
            cp_async16(bb + (tid + i * 256) * 4,
                       fg + (size_t)c * 8192 + (tid + i * 256) * 16);
        CP_COMMIT();
    };

    issue(0);
    issue(1);

    // ---- hoisted: density bias + qbi staging (overlaps with cp.async) ------
    if (tid < 128) {
        float d = dens[b * N + n0 + tid];
        float db;
        if (g_bz) {
            db = d * (d >= 0.f ? g_C1 : g_C2);
        } else {
            db = 0.f;
            for (int j = 0; j < H2; j++)
                db = fmaf(fmaxf(fmaf(d, w1[j], b1[j]), 0.f), w2[j], db);
        }
        sm[SDB_OFF + tid] = db;
    } else if (tid < 192) {
        sm[QBI_OFF + tid - 128] = g_qbi[tid - 128];
    }

#pragma unroll 3
    for (int c = 0; c < 32; c++) {
        CP_WAIT(1);
        __syncthreads();
        if (c + 2 < 32) issue(c + 2);
        int st = c % 3;
        const float* xb = sm + XB(st);
        const uint4* bb4 = (const uint4*)(sm + BBF(st));

#pragma unroll
        for (int s = 0; s < 2; s++) {
            // B fragments: one LDS.128 per (s,j) carries both planes
            uint4 bf[4];
#pragma unroll
            for (int nt = 0; nt < 4; nt++) {
                int j = wn * 4 + nt;
                bf[nt] = bb4[(s * 8 + j) * 32 + l];
            }
#pragma unroll
            for (int mt = 0; mt < 2; mt++) {
                int r  = wm * 32 + mt * 16 + (l >> 2);
                int p  = s * 8 + (l & 3);
                int sw0 = (p     ^ ((r & 3) << 2)) * 2;
                int sw2 = ((p+4) ^ ((r & 3) << 2)) * 2;
                int r8 = r + 8;
                int t0 = (p     ^ ((r8 & 3) << 2)) * 2;
                int t2 = ((p+4) ^ ((r8 & 3) << 2)) * 2;
                float2 A0 = *(const float2*)(xb + r  * 32 + sw0);
                float2 A1 = *(const float2*)(xb + r8 * 32 + t0);
                float2 A2 = *(const float2*)(xb + r  * 32 + sw2);
                float2 A3 = *(const float2*)(xb + r8 * 32 + t2);
                uint32_t a0[4], a1[4];
                a0[0] = pack_h2(A0.x, A0.y); a0[1] = pack_h2(A1.x, A1.y);
                a0[2] = pack_h2(A2.x, A2.y); a0[3] = pack_h2(A3.x, A3.y);
                float2 c0 = unpack_h2(a0[0]), c1 = unpack_h2(a0[1]);
                float2 c2 = unpack_h2(a0[2]), c3 = unpack_h2(a0[3]);
                a1[0] = pack_h2(A0.x - c0.x, A0.y - c0.y);
                a1[1] = pack_h2(A1.x - c1.x, A1.y - c1.y);
                a1[2] = pack_h2(A2.x - c2.x, A2.y - c2.y);
                a1[3] = pack_h2(A3.x - c3.x, A3.y - c3.y);
#pragma unroll
                for (int nt = 0; nt < 4; nt++) {
                    mma_f16(acc[mt][nt], a0, bf[nt].x, bf[nt].y);
                    mma_f16(acc[mt][nt], a0, bf[nt].z, bf[nt].w);
                    mma_f16(acc[mt][nt], a1, bf[nt].x, bf[nt].y);
                }
            }
        }
    }
    __syncthreads();

    // ---- epilogue: bias + stage token-major + store + softmax partials ------
    float* sS = sm;                         // [128 tok][68] = 8704 floats
#pragma unroll
    for (int mt = 0; mt < 2; mt++) {
        int r = wm * 32 + mt * 16 + (l >> 2);
        float d0 = sm[SDB_OFF + r], d1 = sm[SDB_OFF + r + 8];
#pragma unroll
        for (int nt = 0; nt < 4; nt++) {
            int q = wn * 32 + nt * 8 + (l & 3) * 2;
            float t0 = sm[QBI_OFF + q], t1 = sm[QBI_OFF + q + 1];
            sS[r * 68 + q]           = fmaf(acc[mt][nt][0], 0.03125f, t0 + d0);
            sS[r * 68 + q + 1]       = fmaf(acc[mt][nt][1], 0.03125f, t1 + d0);
            sS[(r + 8) * 68 + q]     = fmaf(acc[mt][nt][2], 0.03125f, t0 + d1);
            sS[(r + 8) * 68 + q + 1] = fmaf(acc[mt][nt][3], 0.03125f, t1 + d1);
        }
    }
    __syncthreads();

    {   // token-major coalesced store
        int tok = tid >> 1, h = tid & 1;
        float* dst = g_St + ((size_t)(b * N + n0 + tok)) * 64 + h * 32;
        const float* src = sS + tok * 68 + h * 32;
#pragma unroll
        for (int i = 0; i < 8; i++)
            *(float4*)(dst + i * 4) = *(const float4*)(src + i * 4);
    }

    {   // per-tile softmax partials (pm/pz live in the dead X-buffer region)
        int q = tid & 63, grp = tid >> 6;
        const float* col = sS + (grp * 32) * 68 + q;
        float m = -1e30f;
#pragma unroll
        for (int i = 0; i < 32; i++) m = fmaxf(m, col[i * 68]);
        float z = 0.f;
#pragma unroll
        for (int i = 0; i < 32; i++) z += expf(col[i * 68] - m);
        sm[PM_OFF + grp * 64 + q] = m;
        sm[PZ_OFF + grp * 64 + q] = z;
    }
    __syncthreads();
    if (tid < 64) {
        const float* pm = sm + PM_OFF;
        const float* pz = sm + PZ_OFF;
        float M = pm[tid];
        M = fmaxf(M, pm[64 + tid]);
        M = fmaxf(M, pm[128 + tid]);
        M = fmaxf(M, pm[192 + tid]);
        float Z = 0.f;
#pragma unroll
        for (int g = 0; g < 4; g++)
            Z += pz[g * 64 + tid] * expf(pm[g * 64 + tid] - M);
        g_pmax[(b * 32 + tile) * NQ + tid] = M;
        g_psum[(b * 32 + tile) * NQ + tid] = Z;
    }

    // ---- last CTA of this batch combines the 32 tile partials -> g_c -------
    __threadfence();                      // all writers fence before the count
    __syncthreads();
    if (tid == 0)
        ((int*)(sm + FLAG_OFF))[0] = (atomicAdd(&g_cnt[b], 1) == 31);
    __syncthreads();
    if (((int*)(sm + FLAG_OFF))[0]) {
        __threadfence();
        int q = tid & 63, quar = tid >> 6;            // 4 quarters x 8 tiles
        float M = -1e30f;
#pragma unroll
        for (int t8 = 0; t8 < 8; t8++)
            M = fmaxf(M, g_pmax[(b * 32 + quar * 8 + t8) * NQ + q]);
        sm[PM_OFF + quar * 64 + q] = M;
        __syncthreads();
        float Mg = fmaxf(fmaxf(sm[PM_OFF + q], sm[PM_OFF + 64 + q]),
                         fmaxf(sm[PM_OFF + 128 + q], sm[PM_OFF + 192 + q]));
        float Z = 0.f;
#pragma unroll
        for (int t8 = 0; t8 < 8; t8++) {
            int tl = b * 32 + quar * 8 + t8;
            Z += g_psum[tl * NQ + q] * expf(g_pmax[tl * NQ + q] - Mg);
        }
        sm[PZ_OFF + quar * 64 + q] = Z;
        __syncthreads();
        if (tid < 64) {
            float Zt = sm[PZ_OFF + tid] + sm[PZ_OFF + 64 + tid] +
                       sm[PZ_OFF + 128 + tid] + sm[PZ_OFF + 192 + tid];
            g_c[b * NQ + tid] = Mg + logf(Zt);
        }
    }
}

// ---------------- kernel 3: importance (4 threads/token, streaming) ----------
__global__ void k_imp2() {
    __shared__ float sc[NQ];
    int blk = blockIdx.x, tid = threadIdx.x;
    int b = blk >> 6;                       // 64 blocks per batch
    if (tid < 64) sc[tid] = g_c[b * NQ + tid];
    __syncthreads();
    int tok = (blk & 63) * 64 + (tid >> 2);
    int qt = (tid & 3) * 16;
    const float4* row = (const float4*)(g_St + ((size_t)(b * N + tok)) * 64 + qt);
    float best = -1e30f;
#pragma unroll
    for (int i = 0; i < 4; i++) {
        float4 v = row[i];
        int q = qt + i * 4;
        best = fmaxf(best, fmaxf(fmaxf(v.x - sc[q], v.y - sc[q + 1]),
                                 fmaxf(v.z - sc[q + 2], v.w - sc[q + 3])));
    }
    best = fmaxf(best, __shfl_xor_sync(~0u, best, 1));
    best = fmaxf(best, __shfl_xor_sync(~0u, best, 2));
    if ((tid & 3) == 0) g_imp[b * N + tok] = best;
}

// ---------------- kernel 4: rank + fused compact (last CTA per batch) --------
__global__ void __launch_bounds__(256) k_rank() {
    __shared__ unsigned long long key[N];
    __shared__ int lastflag;
    int b   = blockIdx.x >> 4;
    int seg = blockIdx.x & 15;
    int tid = threadIdx.x;
    for (int i = tid; i < N; i += 256) {
        unsigned u = __float_as_uint(g_imp[b * N + i]);
        u ^= ((unsigned)(((int)u) >> 31)) | 0x80000000u;
        key[i] = ((unsigned long long)u << 12) | (unsigned)(N - 1 - i);
    }
    __syncthreads();
    int i = seg * 256 + tid;
    unsigned long long ki = key[i];
    int r = 0;
#pragma unroll 8
    for (int j = 0; j < N; j++) r += (key[j] > ki);
    g_flag[b * N + i] = (r < TOPK) ? 1 : 0;

    // ---- last CTA of batch compacts indices ----
    __threadfence();
    __syncthreads();
    if (tid == 0) lastflag = (atomicAdd(&g_cnt[8 + b], 1) == 15);
    __syncthreads();
    if (lastflag) {
        __threadfence();
        unsigned* words = (unsigned*)key;           // 128 words (512 B)
        int* pre = (int*)(key + 64);                // 128 ints  (512 B)
#pragma unroll
        for (int cc = 0; cc < 16; cc++) {
            int gi = cc * 256 + tid;
            unsigned bal = __ballot_sync(~0u, g_flag[b * N + gi]);
            if ((tid & 31) == 0) words[gi >> 5] = bal;
        }
        __syncthreads();
        if (tid == 0) {
            int s = 0;
            for (int w = 0; w < 128; w++) { pre[w] = s; s += __popc(words[w]); }
        }
        __syncthreads();
#pragma unroll
        for (int cc = 0; cc < 16; cc++) {
            int gi = cc * 256 + tid;
            unsigned wd = words[gi >> 5];
            if ((wd >> (gi & 31)) & 1u) {
                int slot = pre[gi >> 5] + __popc(wd & ((1u << (gi & 31)) - 1u));
                g_idx[b * TOPK + slot] = gi;
            }
        }
    }
}

// ---------------- kernel 5: gather selected rows -----------------------------
__global__ void k_gather(const float* __restrict__ x, float* __restrict__ out) {
    int row = blockIdx.x;
    int b   = row >> 10;
    int i   = g_idx[row];
    const float4* src = (const float4*)(x + ((size_t)(b * N + i)) * D);
    float4* dst = (float4*)(out + (size_t)row * D);
    dst[threadIdx.x] = src[threadIdx.x];
}

// ---------------- launch -----------------------------------------------------
extern "C" void kernel_launch(void* const* d_in, const int* in_sizes, int n_in,
                              void* d_out, int out_size) {
    const float* tf   = (const float*)d_in[0];
    const float* dens = (const float*)d_in[1];
    const float* qe   = (const float*)d_in[2];
    const float* kw   = (const float*)d_in[3];
    const float* kb   = (const float*)d_in[4];
    const float* w1   = (const float*)d_in[5];
    const float* b1   = (const float*)d_in[6];
    const float* w2   = (const float*)d_in[7];
    const float* b2   = (const float*)d_in[8];
    float* out = (float*)d_out;

    cudaFuncSetAttribute(k_score_tc, cudaFuncAttributeMaxDynamicSharedMemorySize, SCORE_SMEM);

    k_prep<<<130, 256>>>(qe, kw, kb, b2, w1, b1, w2);
    k_bfrag<<<64, 256>>>();
    k_score_tc<<<256, 256, SCORE_SMEM>>>(tf, dens, w1, b1, w2);
    k_imp2<<<512, 256>>>();
    k_rank<<<B * 16, 256>>>();
    k_gather<<<B * TOPK, 256>>>(tf, out);
}

// round 15
// speedup vs baseline: 1.0432x; 1.0432x over previous
#include <cuda_runtime.h>
#include <cuda_fp16.h>
#include <cstdint>

#define B 8
#define N 4096
#define D 1024
#define H 1024
#define NQ 64
#define H2 2048
#define TOPK 1024

// ---------------- scratch ----------------------------------------------------
__device__ __align__(16) float g_QWf[NQ * D];     // fp32 QW [q][d]
__device__ __align__(16) uint2 g_Bfrag[32768];    // fp16 fragment-ordered B
__device__ float g_qbi[NQ];                       // qb/32 + b2
__device__ __align__(16) float g_St[B * N * NQ];  // scores token-major
__device__ float g_pmax[B * 32 * NQ];
__device__ float g_psum[B * 32 * NQ];
__device__ float g_c[B * NQ];                     // logsumexp constants
__device__ float g_imp[B * N];
__device__ int   g_flag[B * N];
__device__ int   g_idx[B * TOPK];
__device__ float g_C1, g_C2;
__device__ int   g_bz;

// ---------------- helpers ----------------------------------------------------
__device__ __forceinline__ uint32_t pack_h2(float a, float b) {
    __half2 h = __floats2half2_rn(a, b);
    return *reinterpret_cast<uint32_t*>(&h);
}
__device__ __forceinline__ float2 unpack_h2(uint32_t u) {
    __half2 h = *reinterpret_cast<__half2*>(&u);
    return __half22float2(h);
}
__device__ __forceinline__ void mma_f16(float* d, const uint32_t* a, uint32_t b0, uint32_t b1) {
    asm volatile("mma.sync.aligned.m16n8k16.row.col.f32.f16.f16.f32 "
        "{%0,%1,%2,%3}, {%4,%5,%6,%7}, {%8,%9}, {%0,%1,%2,%3};"
        : "+f"(d[0]), "+f"(d[1]), "+f"(d[2]), "+f"(d[3])
        : "r"(a[0]), "r"(a[1]), "r"(a[2]), "r"(a[3]), "r"(b0), "r"(b1));
}
__device__ __forceinline__ void cp_async16(void* dst_smem, const void* src) {
    uint32_t d;
    asm("{ .reg .u64 t; cvta.to.shared.u64 t, %1; cvt.u32.u64 %0, t; }" : "=r"(d) : "l"(dst_smem));
    asm volatile("cp.async.cg.shared.global [%0], [%1], 16;" :: "r"(d), "l"(src) : "memory");
}
#define CP_COMMIT() asm volatile("cp.async.commit_group;" ::: "memory")
#define CP_WAIT(n)  asm volatile("cp.async.wait_group %0;" :: "n"(n) : "memory")

// ---------------- kernel 0: prep (QW GEMM + qbi + density consts) ------------
__global__ void __launch_bounds__(256) k_prep(const float* __restrict__ qe,
                                              const float* __restrict__ kw,
                                              const float* __restrict__ kb,
                                              const float* __restrict__ b2,
                                              const float* __restrict__ w1,
                                              const float* __restrict__ b1,
                                              const float* __restrict__ w2) {
    int tid = threadIdx.x;
    int bid = blockIdx.x;
    if (bid < 128) {
        __shared__ float skw[8][68];
        __shared__ float sqt[64][65];
        int d0 = bid * 8;
        int q = tid & 63, dp = tid >> 6;
        float acc0 = 0.f, acc1 = 0.f;
        for (int k0 = 0; k0 < H; k0 += 64) {
#pragma unroll
            for (int r = 0; r < 2; r++) {
                int idx = tid + 256 * r;
                skw[idx >> 6][idx & 63] = kw[(size_t)(d0 + (idx >> 6)) * H + k0 + (idx & 63)];
            }
#pragma unroll
            for (int r = 0; r < 4; r++) {
                int idx = tid + 256 * r;
                int row = idx >> 4, c4 = (idx & 15) * 4;
                float4 v = *(const float4*)(qe + (size_t)row * H + k0 + c4);
                sqt[c4 + 0][row] = v.x; sqt[c4 + 1][row] = v.y;
                sqt[c4 + 2][row] = v.z; sqt[c4 + 3][row] = v.w;
            }
            __syncthreads();
#pragma unroll 8
            for (int k = 0; k < 64; k++) {
                float qv = sqt[k][q];
                acc0 = fmaf(skw[dp][k], qv, acc0);
                acc1 = fmaf(skw[dp + 4][k], qv, acc1);
            }
            __syncthreads();
        }
        g_QWf[(size_t)q * D + d0 + dp] = acc0;
        g_QWf[(size_t)q * D + d0 + dp + 4] = acc1;
    } else if (bid == 128) {
        int w = tid >> 5, l = tid & 31;
        float b2v = b2[0];
#pragma unroll
        for (int qi = 0; qi < 8; qi++) {
            int q = w * 8 + qi;
            float acc = 0.f;
#pragma unroll
            for (int k = 0; k < 32; k++)
                acc = fmaf(qe[(size_t)q * H + k * 32 + l], kb[k * 32 + l], acc);
#pragma unroll
            for (int o = 16; o; o >>= 1) acc += __shfl_xor_sync(~0u, acc, o);
            if (l == 0) g_qbi[q] = acc * 0.03125f + b2v;
        }
    } else {
        __shared__ float r1[256], r2[256];
        __shared__ int rz[256];
        float c1 = 0.f, c2 = 0.f; int bz = 1;
        for (int j = tid; j < H2; j += 256) {
            float a = w1[j], c = w2[j];
            if (a > 0.f) c1 += a * c; else c2 += a * c;
            if (b1[j] != 0.f) bz = 0;
        }
        r1[tid] = c1; r2[tid] = c2; rz[tid] = bz;
        __syncthreads();
        for (int o = 128; o; o >>= 1) {
            if (tid < o) { r1[tid] += r1[tid + o]; r2[tid] += r2[tid + o]; rz[tid] &= rz[tid + o]; }
            __syncthreads();
        }
        if (tid == 0) { g_C1 = r1[0]; g_C2 = r2[0]; g_bz = rz[0]; }
    }
}

// ---------------- kernel 1: pack B into fp16 fragment order ------------------
__global__ void k_bfrag() {
    int t = blockIdx.x * 256 + threadIdx.x;   // < 32768
    int lane = t & 31, pl = (t >> 5) & 1, j = (t >> 6) & 7, s = (t >> 9) & 1, c = t >> 10;
    int q = j * 8 + (lane >> 2);
    int k0 = c * 32 + s * 16 + (lane & 3) * 2;
    const float* w = g_QWf + (size_t)q * D + k0;
    float f0 = w[0], f1 = w[1], f2 = w[8], f3 = w[9];
    uint32_t ha = pack_h2(f0, f1), hb = pack_h2(f2, f3);
    if (pl == 0) {
        g_Bfrag[t] = make_uint2(ha, hb);
    } else {
        float2 ca = unpack_h2(ha), cb = unpack_h2(hb);
        g_Bfrag[t] = make_uint2(pack_h2(f0 - ca.x, f1 - ca.y),
                                pack_h2(f2 - cb.x, f3 - cb.y));
    }
}

// ---------------- kernel 2: score GEMM (3-stage, frag-B, inline dbias) -------
// float offsets in dynamic smem
#define XB(s)  ((s) * 4096)            // 3 X buffers, 128 rows x 32 (swizzled)
#define PM_OFF 9216                    // inside XB region; free after mainloop
#define PZ_OFF 9472
#define BBF(s) (12288 + (s) * 2048)    // 3 B fragment buffers (1024 uint2)
#define SDB_OFF 18432
#define QBI_OFF 18560
#define SCORE_SMEM 74496               // 18624 floats

__global__ void __launch_bounds__(256, 2) k_score_tc(const float* __restrict__ x,
                                                     const float* __restrict__ dens,
                                                     const float* __restrict__ w1,
                                                     const float* __restrict__ b1,
                                                     const float* __restrict__ w2) {
    extern __shared__ float sm[];
    int tid = threadIdx.x, w = tid >> 5, l = tid & 31;
    int b = blockIdx.x >> 5, tile = blockIdx.x & 31;
    int n0 = tile << 7;
    int wm = w & 3, wn = w >> 2;
    const char* xg = (const char*)(x + ((size_t)(b * N + n0)) * D);
    const char* fg = (const char*)g_Bfrag;

    float acc[2][4][4] = {};

    int xrow = tid >> 1;                 // 0..127
    int xc0  = (tid & 1) * 4;            // chunk base 0 or 4

    auto issue = [&](int c) {
        int st = c % 3;
        float* xb = sm + XB(st);
        float* bb = sm + BBF(st);
#pragma unroll
        for (int i = 0; i < 4; i++) {
            int ch = xc0 + i;
            int chs = ch ^ ((xrow & 3) << 1);           // swizzled 16B chunk
            cp_async16(xb + xrow * 32 + chs * 4,
                       xg + (size_t)xrow * 4096 + (size_t)c * 128 + ch * 16);
        }
#pragma unroll
        for (int i = 0; i < 2; i++)
            cp_async16(bb + (tid + i * 256) * 4,
                       fg + (size_t)c * 8192 + (tid + i * 256) * 16);
        CP_COMMIT();
    };

    issue(0);
    issue(1);

    // ---- hoisted: density bias + qbi staging (overlaps with cp.async) ------
    if (tid < 128) {
        float d = dens[b * N + n0 + tid];
        float db;
        if (g_bz) {
            db = d * (d >= 0.f ? g_C1 : g_C2);
        } else {
            db = 0.f;
            for (int j = 0; j < H2; j++)
                db = fmaf(fmaxf(fmaf(d, w1[j], b1[j]), 0.f), w2[j], db);
        }
        sm[SDB_OFF + tid] = db;
    } else if (tid < 192) {
        sm[QBI_OFF + tid - 128] = g_qbi[tid - 128];
    }

#pragma unroll 3
    for (int c = 0; c < 32; c++) {
        CP_WAIT(1);
        __syncthreads();
        if (c + 2 < 32) issue(c + 2);
        int st = c % 3;
        const float* xb = sm + XB(st);
        const uint2* bb = (const uint2*)(sm + BBF(st));

#pragma unroll
        for (int s = 0; s < 2; s++) {
            // B fragments from smem (pre-split planes)
            uint2 b0f[4], b1f[4];
#pragma unroll
            for (int nt = 0; nt < 4; nt++) {
                int j = wn * 4 + nt;
                b0f[nt] = bb[((s * 8 + j) * 2 + 0) * 32 + l];
                b1f[nt] = bb[((s * 8 + j) * 2 + 1) * 32 + l];
            }
#pragma unroll
            for (int mt = 0; mt < 2; mt++) {
                int r  = wm * 32 + mt * 16 + (l >> 2);
                int p  = s * 8 + (l & 3);
                int sw0 = (p     ^ ((r & 3) << 2)) * 2;
                int sw2 = ((p+4) ^ ((r & 3) << 2)) * 2;
                int r8 = r + 8;
                int t0 = (p     ^ ((r8 & 3) << 2)) * 2;
                int t2 = ((p+4) ^ ((r8 & 3) << 2)) * 2;
                float2 A0 = *(const float2*)(xb + r  * 32 + sw0);
                float2 A1 = *(const float2*)(xb + r8 * 32 + t0);
                float2 A2 = *(const float2*)(xb + r  * 32 + sw2);
                float2 A3 = *(const float2*)(xb + r8 * 32 + t2);
                uint32_t a0[4], a1[4];
                a0[0] = pack_h2(A0.x, A0.y); a0[1] = pack_h2(A1.x, A1.y);
                a0[2] = pack_h2(A2.x, A2.y); a0[3] = pack_h2(A3.x, A3.y);
                float2 c0 = unpack_h2(a0[0]), c1 = unpack_h2(a0[1]);
                float2 c2 = unpack_h2(a0[2]), c3 = unpack_h2(a0[3]);
                a1[0] = pack_h2(A0.x - c0.x, A0.y - c0.y);
                a1[1] = pack_h2(A1.x - c1.x, A1.y - c1.y);
                a1[2] = pack_h2(A2.x - c2.x, A2.y - c2.y);
                a1[3] = pack_h2(A3.x - c3.x, A3.y - c3.y);
#pragma unroll
                for (int nt = 0; nt < 4; nt++) {
                    mma_f16(acc[mt][nt], a0, b0f[nt].x, b0f[nt].y);
                    mma_f16(acc[mt][nt], a0, b1f[nt].x, b1f[nt].y);
                    mma_f16(acc[mt][nt], a1, b0f[nt].x, b0f[nt].y);
                }
            }
        }
    }
    __syncthreads();

    // ---- epilogue: bias + stage token-major + store + softmax partials ------
    float* sS = sm;                         // [128 tok][68] = 8704 floats
#pragma unroll
    for (int mt = 0; mt < 2; mt++) {
        int r = wm * 32 + mt * 16 + (l >> 2);
        float d0 = sm[SDB_OFF + r], d1 = sm[SDB_OFF + r + 8];
#pragma unroll
        for (int nt = 0; nt < 4; nt++) {
            int q = wn * 32 + nt * 8 + (l & 3) * 2;
            float t0 = sm[QBI_OFF + q], t1 = sm[QBI_OFF + q + 1];
            sS[r * 68 + q]           = fmaf(acc[mt][nt][0], 0.03125f, t0 + d0);
            sS[r * 68 + q + 1]       = fmaf(acc[mt][nt][1], 0.03125f, t1 + d0);
            sS[(r + 8) * 68 + q]     = fmaf(acc[mt][nt][2], 0.03125f, t0 + d1);
            sS[(r + 8) * 68 + q + 1] = fmaf(acc[mt][nt][3], 0.03125f, t1 + d1);
        }
    }
    __syncthreads();

    {   // token-major coalesced store
        int tok = tid >> 1, h = tid & 1;
        float* dst = g_St + ((size_t)(b * N + n0 + tok)) * 64 + h * 32;
        const float* src = sS + tok * 68 + h * 32;
#pragma unroll
        for (int i = 0; i < 8; i++)
            *(float4*)(dst + i * 4) = *(const float4*)(src + i * 4);
    }

    {   // per-tile softmax partials (pm/pz live in the dead X-buffer region)
        int q = tid & 63, grp = tid >> 6;
        const float* col = sS + (grp * 32) * 68 + q;
        float m = -1e30f;
#pragma unroll
        for (int i = 0; i < 32; i++) m = fmaxf(m, col[i * 68]);
        float z = 0.f;
#pragma unroll
        for (int i = 0; i < 32; i++) z += expf(col[i * 68] - m);
        sm[PM_OFF + grp * 64 + q] = m;
        sm[PZ_OFF + grp * 64 + q] = z;
    }
    __syncthreads();
    if (tid < 64) {
        const float* pm = sm + PM_OFF;
        const float* pz = sm + PZ_OFF;
        float M = pm[tid];
        M = fmaxf(M, pm[64 + tid]);
        M = fmaxf(M, pm[128 + tid]);
        M = fmaxf(M, pm[192 + tid]);
        float Z = 0.f;
#pragma unroll
        for (int g = 0; g < 4; g++)
            Z += pz[g * 64 + tid] * expf(pm[g * 64 + tid] - M);
        g_pmax[(b * 32 + tile) * NQ + tid] = M;
        g_psum[(b * 32 + tile) * NQ + tid] = Z;
    }
}

// ---------------- kernel 3: combine tile partials -> g_c ---------------------
__global__ void k_combine() {
    int t = blockIdx.x * 256 + threadIdx.x;   // < 512
    int b = t >> 6, q = t & 63;
    float M = -1e30f;
#pragma unroll 8
    for (int tl = 0; tl < 32; tl++)
        M = fmaxf(M, g_pmax[(b * 32 + tl) * NQ + q]);
    float Z = 0.f;
#pragma unroll 8
    for (int tl = 0; tl < 32; tl++)
        Z += g_psum[(b * 32 + tl) * NQ + q] * expf(g_pmax[(b * 32 + tl) * NQ + q] - M);
    g_c[b * NQ + q] = M + logf(Z);
}

// ---------------- kernel 4: importance (4 threads/token, streaming) ----------
__global__ void k_imp2() {
    __shared__ float sc[NQ];
    int blk = blockIdx.x, tid = threadIdx.x;
    int b = blk >> 6;                       // 64 blocks per batch
    if (tid < 64) sc[tid] = g_c[b * NQ + tid];
    __syncthreads();
    int tok = (blk & 63) * 64 + (tid >> 2);
    int qt = (tid & 3) * 16;
    const float4* row = (const float4*)(g_St + ((size_t)(b * N + tok)) * 64 + qt);
    float best = -1e30f;
#pragma unroll
    for (int i = 0; i < 4; i++) {
        float4 v = row[i];
        int q = qt + i * 4;
        best = fmaxf(best, fmaxf(fmaxf(v.x - sc[q], v.y - sc[q + 1]),
                                 fmaxf(v.z - sc[q + 2], v.w - sc[q + 3])));
    }
    best = fmaxf(best, __shfl_xor_sync(~0u, best, 1));
    best = fmaxf(best, __shfl_xor_sync(~0u, best, 2));
    if ((tid & 3) == 0) g_imp[b * N + tok] = best;
}

// ---------------- kernel 5: exact rank (stable top-k) ------------------------
__global__ void __launch_bounds__(256) k_rank() {
    __shared__ unsigned long long key[N];
    int b   = blockIdx.x >> 4;
    int seg = blockIdx.x & 15;
    int tid = threadIdx.x;
    for (int i = tid; i < N; i += 256) {
        unsigned u = __float_as_uint(g_imp[b * N + i]);
        u ^= ((unsigned)(((int)u) >> 31)) | 0x80000000u;
        key[i] = ((unsigned long long)u << 12) | (unsigned)(N - 1 - i);
    }
    __syncthreads();
    int i = seg * 256 + tid;
    unsigned long long ki = key[i];
    int r = 0;
#pragma unroll 8
    for (int j = 0; j < N; j++) r += (key[j] > ki);
    g_flag[b * N + i] = (r < TOPK) ? 1 : 0;
}

// ---------------- kernel 6: compact selected indices -------------------------
__global__ void k_compact() {
    __shared__ unsigned words[N / 32];
    __shared__ int pre[N / 32];
    int b   = blockIdx.x;
    int tid = threadIdx.x;
#pragma unroll
    for (int cc = 0; cc < N / 1024; cc++) {
        int gi = cc * 1024 + tid;
        unsigned bal = __ballot_sync(~0u, g_flag[b * N + gi]);
        if ((tid & 31) == 0) words[gi >> 5] = bal;
    }
    __syncthreads();
    if (tid == 0) {
        int s = 0;
        for (int w = 0; w < N / 32; w++) { pre[w] = s; s += __popc(words[w]); }
    }
    __syncthreads();
#pragma unroll
    for (int cc = 0; cc < N / 1024; cc++) {
        int gi = cc * 1024 + tid;
        unsigned w = words[gi >> 5];
        if ((w >> (gi & 31)) & 1u) {
            int slot = pre[gi >> 5] + __popc(w & ((1u << (gi & 31)) - 1u));
            g_idx[b * TOPK + slot] = gi;
        }
    }
}

// ---------------- kernel 7: gather selected rows -----------------------------
__global__ void k_gather(const float* __restrict__ x, float* __restrict__ out) {
    int row = blockIdx.x;
    int b   = row >> 10;
    int i   = g_idx[row];
    const float4* src = (const float4*)(x + ((size_t)(b * N + i)) * D);
    float4* dst = (float4*)(out + (size_t)row * D);
    dst[threadIdx.x] = src[threadIdx.x];
}

// ---------------- launch -----------------------------------------------------
extern "C" void kernel_launch(void* const* d_in, const int* in_sizes, int n_in,
                              void* d_out, int out_size) {
    const float* tf   = (const float*)d_in[0];
    const float* dens = (const float*)d_in[1];
    const float* qe   = (const float*)d_in[2];
    const float* kw   = (const float*)d_in[3];
    const float* kb   = (const float*)d_in[4];
    const float* w1   = (const float*)d_in[5];
    const float* b1   = (const float*)d_in[6];
    const float* w2   = (const float*)d_in[7];
    const float* b2   = (const float*)d_in[8];
    float* out = (float*)d_out;

    cudaFuncSetAttribute(k_score_tc, cudaFuncAttributeMaxDynamicSharedMemorySize, SCORE_SMEM);

    k_prep<<<130, 256>>>(qe, kw, kb, b2, w1, b1, w2);
    k_bfrag<<<128, 256>>>();
    k_score_tc<<<256, 256, SCORE_SMEM>>>(tf, dens, w1, b1, w2);
    k_combine<<<2, 256>>>();
    k_imp2<<<512, 256>>>();
    k_rank<<<B * 16, 256>>>();
    k_compact<<<B, 1024>>>();
    k_gather<<<B * TOPK, 256>>>(tf, out);
}